// round 13
// baseline (speedup 1.0000x reference)
#include <cuda_runtime.h>
#include <cuda_fp16.h>
#include <math.h>
#include <stdint.h>

// ---------------- problem-size scratch (device globals: allocation-free) ----
#define NMAX 100000
#define EMAX 1600000
#define SCAN_TILE 4096
#define MAX_SCAN_BLOCKS ((NMAX + SCAN_TILE - 1) / SCAN_TILE)
#define BFRAG1 (16 * 16 * 64)
#define BFRAG2 (16 * 8 * 64)

__device__ __half g_xw1h[NMAX * 128]; // (x @ W1) * dinv[row], fp16
__device__ float  g_h   [NMAX * 128]; // layer-1 output (post agg+bias+relu)
__device__ __half g_xw2h[NMAX * 64];  // (h @ W2) * dinv[row], fp16
__device__ float  g_dinv[NMAX];       // rsqrt(in_degree + 1)
__device__ int    g_cnt[NMAX];
__device__ int    g_rowptr[NMAX + 1];
__device__ int    g_cursor[NMAX];
__device__ int    g_csr[EMAX];
__device__ int    g_is64;
// packed lookback tile state: bits[63:62] = {0 invalid, 1 aggregate, 2 inclusive},
// bits[31:0] = value. Single 8-byte word -> flag+value read atomically.
__device__ unsigned long long g_tile[MAX_SCAN_BLOCKS];
__device__ float  g_bf1[BFRAG1];      // W1 mma fragments
__device__ float  g_bf2[BFRAG2];      // W2 mma fragments

// ---------------- mma / async helpers ----------------------------------------
__device__ __forceinline__ float cvt_tf32(float x) {
    uint32_t r; asm("cvt.rna.tf32.f32 %0, %1;" : "=r"(r) : "f"(x));
    return __uint_as_float(r);
}
__device__ __forceinline__ uint32_t smem_u32(const void* p) {
    return (uint32_t)__cvta_generic_to_shared(p);
}
__device__ __forceinline__ void ldsm4(uint32_t& r0, uint32_t& r1, uint32_t& r2,
                                      uint32_t& r3, uint32_t a) {
    asm volatile("ldmatrix.sync.aligned.m8n8.x4.shared.b16 {%0,%1,%2,%3}, [%4];"
                 : "=r"(r0), "=r"(r1), "=r"(r2), "=r"(r3) : "r"(a));
}
__device__ __forceinline__ void mma_tf32(float c[4], const uint32_t a[4],
                                         uint32_t b0, uint32_t b1) {
    asm volatile("mma.sync.aligned.m16n8k8.row.col.f32.tf32.tf32.f32 "
                 "{%0,%1,%2,%3}, {%4,%5,%6,%7}, {%8,%9}, {%0,%1,%2,%3};"
                 : "+f"(c[0]), "+f"(c[1]), "+f"(c[2]), "+f"(c[3])
                 : "r"(a[0]), "r"(a[1]), "r"(a[2]), "r"(a[3]), "r"(b0), "r"(b1));
}
__device__ __forceinline__ void cp_async16(uint32_t dst, const void* src, bool pred) {
    int sz = pred ? 16 : 0;
    asm volatile("cp.async.cg.shared.global [%0], [%1], 16, %2;"
                 :: "r"(dst), "l"(src), "r"(sz));
}
__device__ __forceinline__ void cp_commit() {
    asm volatile("cp.async.commit_group;");
}
template <int n>
__device__ __forceinline__ void cp_wait() {
    asm volatile("cp.async.wait_group %0;" :: "n"(n));
}

// ---------------- fused init: zero cnt + bfrag + detect + tile reset ---------
__global__ void k_init(const float* __restrict__ W1, const float* __restrict__ W2,
                       const long long* __restrict__ ei, int E, int N) {
    int t = blockIdx.x * blockDim.x + threadIdx.x;
    if (t < N) g_cnt[t] = 0;
    if (t < MAX_SCAN_BLOCKS) *((volatile unsigned long long*)&g_tile[t]) = 0ull;
    if (t < BFRAG1) {
        int j    = t & 1;
        int lane = (t >> 1) & 31;
        int nf   = (t >> 6) & 15;
        int ks   = t >> 10;
        int k = ks * 8 + (lane & 3) + j * 4;
        int n = nf * 8 + (lane >> 2);
        g_bf1[t] = cvt_tf32(W1[k * 128 + n]);
    } else if (t < BFRAG1 + BFRAG2) {
        int u = t - BFRAG1;
        int j    = u & 1;
        int lane = (u >> 1) & 31;
        int nf   = (u >> 6) & 7;
        int ks   = u >> 9;
        int k = ks * 8 + (lane & 3) + j * 4;
        int n = nf * 8 + (lane >> 2);
        g_bf2[u] = cvt_tf32(W2[k * 64 + n]);
    }
    if (blockIdx.x == 0 && threadIdx.x < 32) {
        int lane = threadIdx.x;
        int lim = E < 64 ? E : 64;
        bool bad = false;
        for (int j = lane; j < lim; j += 32) {
            long long v = ei[j];
            if (v < 0 || v >= (long long)N) bad = true;
        }
        unsigned m = __ballot_sync(0xffffffffu, bad);
        if (lane == 0) g_is64 = (m == 0) ? 1 : 0;
    }
}

// ---------------- histogram (2 edges/thread, vectorized) ---------------------
__global__ void k_hist(const void* __restrict__ ei, int E, int N) {
    int i = (blockIdx.x * blockDim.x + threadIdx.x) * 2;
    if (i >= E) return;
    int d0, d1 = -1;
    if (g_is64) {
        const long long* p = (const long long*)ei + E;
        if (i + 1 < E) {
            longlong2 v = *(const longlong2*)(p + i);
            d0 = (int)v.x; d1 = (int)v.y;
        } else d0 = (int)p[i];
    } else {
        const int* p = (const int*)ei + E;
        if (i + 1 < E) {
            int2 v = *(const int2*)(p + i);
            d0 = v.x; d1 = v.y;
        } else d0 = p[i];
    }
    if (d0 < 0 || d0 >= N) d0 = 0;
    if (i + 1 < E) {
        if (d1 < 0 || d1 >= N) d1 = 0;
        if (d1 == d0) { atomicAdd(&g_cnt[d0], 2); return; }
        atomicAdd(&g_cnt[d1], 1);
    }
    atomicAdd(&g_cnt[d0], 1);
}

// ---------------- single-pass scan (packed-word decoupled lookback) ----------
__global__ __launch_bounds__(1024) void k_scan(int N) {
    __shared__ int wsum[32];
    __shared__ int s_off;
    const int lane = threadIdx.x & 31;
    const int wid  = threadIdx.x >> 5;
    const int bid  = blockIdx.x;
    const int base = bid * SCAN_TILE + threadIdx.x * 4;

    int v0 = 0, v1 = 0, v2 = 0, v3 = 0;
    if (base + 3 < N) {
        v0 = g_cnt[base]; v1 = g_cnt[base + 1];
        v2 = g_cnt[base + 2]; v3 = g_cnt[base + 3];
    } else {
        if (base     < N) v0 = g_cnt[base];
        if (base + 1 < N) v1 = g_cnt[base + 1];
        if (base + 2 < N) v2 = g_cnt[base + 2];
        if (base + 3 < N) v3 = g_cnt[base + 3];
    }
    int p0 = v0, p1 = p0 + v1, p2 = p1 + v2, p3 = p2 + v3;
    int x = p3;
    #pragma unroll
    for (int o = 1; o < 32; o <<= 1) {
        int y = __shfl_up_sync(0xffffffffu, x, o);
        if (lane >= o) x += y;
    }
    if (lane == 31) wsum[wid] = x;
    __syncthreads();
    if (wid == 0) {
        int w = wsum[lane];
        #pragma unroll
        for (int o = 1; o < 32; o <<= 1) {
            int y = __shfl_up_sync(0xffffffffu, w, o);
            if (lane >= o) w += y;
        }
        wsum[lane] = w;
    }
    __syncthreads();
    int texcl = (x - p3) + (wid ? wsum[wid - 1] : 0);
    int btotal = wsum[31];

    if (threadIdx.x == 0) {
        volatile unsigned long long* tile = (volatile unsigned long long*)g_tile;
        if (bid == 0) {
            tile[0] = (2ull << 62) | (unsigned int)btotal;   // inclusive
            s_off = 0;
        } else {
            tile[bid] = (1ull << 62) | (unsigned int)btotal; // aggregate
            int off = 0;
            for (int p = bid - 1; p >= 0; p--) {
                unsigned long long tv;
                do { tv = tile[p]; } while ((tv >> 62) == 0);
                off += (int)(unsigned int)(tv & 0xffffffffull);
                if ((tv >> 62) == 2) break;
            }
            tile[bid] = (2ull << 62) | (unsigned int)(off + btotal);
            s_off = off;
        }
    }
    __syncthreads();
    int off = s_off;
    if (bid == 0 && threadIdx.x == 0) g_rowptr[0] = 0;
    if (base < N) {
        int incl = off + texcl + p0;
        g_rowptr[base + 1] = incl;
        g_cursor[base]     = incl - v0;
        g_dinv[base]       = rsqrtf((float)(v0 + 1));
    }
    if (base + 1 < N) {
        int incl = off + texcl + p1;
        g_rowptr[base + 2] = incl;
        g_cursor[base + 1] = incl - v1;
        g_dinv[base + 1]   = rsqrtf((float)(v1 + 1));
    }
    if (base + 2 < N) {
        int incl = off + texcl + p2;
        g_rowptr[base + 3] = incl;
        g_cursor[base + 2] = incl - v2;
        g_dinv[base + 2]   = rsqrtf((float)(v2 + 1));
    }
    if (base + 3 < N) {
        int incl = off + texcl + p3;
        g_rowptr[base + 4] = incl;
        g_cursor[base + 3] = incl - v3;
        g_dinv[base + 3]   = rsqrtf((float)(v3 + 1));
    }
}

// ---------------- scatter (2 edges/thread, vectorized reads) -----------------
__global__ void k_scatter(const void* __restrict__ ei, int E, int N) {
    int i = (blockIdx.x * blockDim.x + threadIdx.x) * 2;
    if (i >= E) return;
    int s0, d0, s1 = -1, d1 = -1;
    bool two = (i + 1 < E);
    if (g_is64) {
        const long long* ps = (const long long*)ei;
        const long long* pd = ps + E;
        if (two) {
            longlong2 vs = *(const longlong2*)(ps + i);
            longlong2 vd = *(const longlong2*)(pd + i);
            s0 = (int)vs.x; s1 = (int)vs.y; d0 = (int)vd.x; d1 = (int)vd.y;
        } else { s0 = (int)ps[i]; d0 = (int)pd[i]; }
    } else {
        const int* ps = (const int*)ei;
        const int* pd = ps + E;
        if (two) {
            int2 vs = *(const int2*)(ps + i);
            int2 vd = *(const int2*)(pd + i);
            s0 = vs.x; s1 = vs.y; d0 = vd.x; d1 = vd.y;
        } else { s0 = ps[i]; d0 = pd[i]; }
    }
    if (s0 < 0 || s0 >= N) s0 = 0;
    if (d0 < 0 || d0 >= N) d0 = 0;
    int p0 = atomicAdd(&g_cursor[d0], 1);
    if (p0 >= 0 && p0 < EMAX) g_csr[p0] = s0;
    if (two) {
        if (s1 < 0 || s1 >= N) s1 = 0;
        if (d1 < 0 || d1 >= N) d1 = 0;
        int p1 = atomicAdd(&g_cursor[d1], 1);
        if (p1 >= 0 && p1 < EMAX) g_csr[p1] = s1;
    }
}

// ---------------- tensor-core GEMM (cp.async pipelined) ----------------------
// Ch[M,BN] = (A[M,128] @ W) * dinv, fp16 out.
// K split into 4 chunks of 32 cols, double-buffered cp.async staging.
template <int BN>
__global__ __launch_bounds__(256, 2) void k_gemm_tc(const float* __restrict__ A,
                                                    const float* __restrict__ BF,
                                                    __half* __restrict__ C,
                                                    const float* __restrict__ dinv,
                                                    int M) {
    constexpr int NFTOT = BN / 8;
    constexpr int NF    = NFTOT / 2;
    constexpr int LDA   = 36;         // 32 + 4 pad floats; row stride 144B
    constexpr int CHUNKS = 4;
    __shared__ float As[2][128 * LDA];

    const int tid  = threadIdx.x;
    const int lane = tid & 31;
    const int wid  = tid >> 5;
    const int wm   = wid & 3;
    const int wn   = wid >> 2;
    const int m0   = blockIdx.x * 128;
    const int q    = tid & 7;          // float4 slot within 32-col chunk
    const int rr   = tid >> 3;         // base row (0..31), step 32

    float c[2][NF][4];
    #pragma unroll
    for (int mf = 0; mf < 2; mf++)
        #pragma unroll
        for (int nf = 0; nf < NF; nf++)
            #pragma unroll
            for (int i = 0; i < 4; i++) c[mf][nf][i] = 0.f;

    uint32_t a_base[2];
    #pragma unroll
    for (int b = 0; b < 2; b++)
        a_base[b] = smem_u32(As[b]) +
                    (((wm * 32 + (lane & 15)) * LDA + (lane >> 4) * 4) << 2);
    uint32_t s_base[2];
    #pragma unroll
    for (int b = 0; b < 2; b++)
        s_base[b] = smem_u32(As[b]);

    // prefetch chunk 0
    {
        #pragma unroll
        for (int it = 0; it < 4; it++) {
            int r  = rr + it * 32;
            int gm = m0 + r;
            cp_async16(s_base[0] + ((r * LDA + q * 4) << 2),
                       A + (size_t)gm * 128 + 0 * 32 + q * 4, gm < M);
        }
        cp_commit();
    }

    #pragma unroll
    for (int ch = 0; ch < CHUNKS; ch++) {
        if (ch + 1 < CHUNKS) {
            int nb = (ch + 1) & 1;
            #pragma unroll
            for (int it = 0; it < 4; it++) {
                int r  = rr + it * 32;
                int gm = m0 + r;
                cp_async16(s_base[nb] + ((r * LDA + q * 4) << 2),
                           A + (size_t)gm * 128 + (ch + 1) * 32 + q * 4, gm < M);
            }
            cp_commit();
            cp_wait<1>();
        } else {
            cp_wait<0>();
        }
        __syncthreads();

        const int cb = ch & 1;
        #pragma unroll
        for (int ks = 0; ks < 4; ks++) {
            uint32_t a[2][4];
            #pragma unroll
            for (int mf = 0; mf < 2; mf++)
                ldsm4(a[mf][0], a[mf][1], a[mf][2], a[mf][3],
                      a_base[cb] + mf * (16 * LDA * 4) + ks * 32);
            int ksg = ch * 4 + ks;
            #pragma unroll
            for (int nf = 0; nf < NF; nf++) {
                float2 b = __ldg((const float2*)BF +
                                 (size_t)(ksg * NFTOT + wn * NF + nf) * 32 + lane);
                uint32_t b0 = __float_as_uint(b.x), b1 = __float_as_uint(b.y);
                mma_tf32(c[0][nf], a[0], b0, b1);
                mma_tf32(c[1][nf], a[1], b0, b1);
            }
        }
        __syncthreads();
    }

    // epilogue: * dinv[row], fp16 store
    #pragma unroll
    for (int mf = 0; mf < 2; mf++) {
        int r0 = m0 + wm * 32 + mf * 16 + (lane >> 2);
        int cb = wn * (BN / 2) + (lane & 3) * 2;
        float d0 = (r0 < M)     ? dinv[r0]     : 0.f;
        float d1 = (r0 + 8 < M) ? dinv[r0 + 8] : 0.f;
        #pragma unroll
        for (int nf = 0; nf < NF; nf++) {
            int n = cb + nf * 8;
            if (r0 < M)
                *(__half2*)(C + (size_t)r0 * BN + n) =
                    __floats2half2_rn(c[mf][nf][0] * d0, c[mf][nf][1] * d0);
            if (r0 + 8 < M)
                *(__half2*)(C + (size_t)(r0 + 8) * BN + n) =
                    __floats2half2_rn(c[mf][nf][2] * d1, c[mf][nf][3] * d1);
        }
    }
}

// ---------------- layer-1 aggregation + bias + ReLU (F=128, fp16 gather) ----
__global__ __launch_bounds__(256) void k_agg1(const __half* __restrict__ xwh,
                                              const float* __restrict__ bias,
                                              float* __restrict__ out, int N, int E) {
    int node = blockIdx.x * (blockDim.x >> 5) + (threadIdx.x >> 5);
    if (node >= N) return;
    int lane = threadIdx.x & 31;
    float di = g_dinv[node];

    uint2 u = ((const uint2*)(xwh + (size_t)node * 128))[lane];
    float2 q0 = __half22float2(*(const __half2*)&u.x);
    float2 q1 = __half22float2(*(const __half2*)&u.y);
    float4 acc = make_float4(q0.x, q0.y, q1.x, q1.y);

    int e = g_rowptr[node], end = g_rowptr[node + 1];
    if (e < 0) e = 0;
    if (end > E) end = E;
    for (; e + 1 < end; e += 2) {
        int s0 = g_csr[e], s1 = g_csr[e + 1];
        uint2 a = ((const uint2*)(xwh + (size_t)s0 * 128))[lane];
        uint2 b = ((const uint2*)(xwh + (size_t)s1 * 128))[lane];
        float2 a0 = __half22float2(*(const __half2*)&a.x);
        float2 a1 = __half22float2(*(const __half2*)&a.y);
        float2 b0 = __half22float2(*(const __half2*)&b.x);
        float2 b1 = __half22float2(*(const __half2*)&b.y);
        acc.x += a0.x + b0.x;
        acc.y += a0.y + b0.y;
        acc.z += a1.x + b1.x;
        acc.w += a1.y + b1.y;
    }
    if (e < end) {
        int s = g_csr[e];
        uint2 a = ((const uint2*)(xwh + (size_t)s * 128))[lane];
        float2 a0 = __half22float2(*(const __half2*)&a.x);
        float2 a1 = __half22float2(*(const __half2*)&a.y);
        acc.x += a0.x; acc.y += a0.y; acc.z += a1.x; acc.w += a1.y;
    }
    float4 bb = ((const float4*)bias)[lane];
    float4 r;
    r.x = fmaxf(fmaf(acc.x, di, bb.x), 0.f);
    r.y = fmaxf(fmaf(acc.y, di, bb.y), 0.f);
    r.z = fmaxf(fmaf(acc.z, di, bb.z), 0.f);
    r.w = fmaxf(fmaf(acc.w, di, bb.w), 0.f);
    ((float4*)(out + (size_t)node * 128))[lane] = r;
}

// ---------------- layer-2 aggregation + bias + log_softmax (F=64, fp16) -----
__global__ __launch_bounds__(256) void k_agg2(const __half* __restrict__ xwh,
                                              const float* __restrict__ bias,
                                              float* __restrict__ out, int N, int E) {
    int node = blockIdx.x * (blockDim.x >> 5) + (threadIdx.x >> 5);
    if (node >= N) return;
    int lane = threadIdx.x & 31;
    float di = g_dinv[node];

    unsigned u = ((const unsigned*)(xwh + (size_t)node * 64))[lane];
    float2 acc = __half22float2(*(const __half2*)&u);

    int e = g_rowptr[node], end = g_rowptr[node + 1];
    if (e < 0) e = 0;
    if (end > E) end = E;
    for (; e + 1 < end; e += 2) {
        int s0 = g_csr[e], s1 = g_csr[e + 1];
        unsigned a = ((const unsigned*)(xwh + (size_t)s0 * 64))[lane];
        unsigned b = ((const unsigned*)(xwh + (size_t)s1 * 64))[lane];
        float2 av = __half22float2(*(const __half2*)&a);
        float2 bv = __half22float2(*(const __half2*)&b);
        acc.x += av.x + bv.x;
        acc.y += av.y + bv.y;
    }
    if (e < end) {
        int s = g_csr[e];
        unsigned a = ((const unsigned*)(xwh + (size_t)s * 64))[lane];
        float2 av = __half22float2(*(const __half2*)&a);
        acc.x += av.x; acc.y += av.y;
    }
    float2 bb = ((const float2*)bias)[lane];
    float vx = fmaf(acc.x, di, bb.x);
    float vy = fmaf(acc.y, di, bb.y);

    float m = fmaxf(vx, vy);
    #pragma unroll
    for (int o = 16; o; o >>= 1) m = fmaxf(m, __shfl_xor_sync(0xffffffffu, m, o));
    float s = expf(vx - m) + expf(vy - m);
    #pragma unroll
    for (int o = 16; o; o >>= 1) s += __shfl_xor_sync(0xffffffffu, s, o);
    float lse = m + logf(s);
    ((float2*)(out + (size_t)node * 64))[lane] = make_float2(vx - lse, vy - lse);
}

// ---------------- launcher ---------------------------------------------------
extern "C" void kernel_launch(void* const* d_in, const int* in_sizes, int n_in,
                              void* d_out, int out_size) {
    const float* x   = (const float*)d_in[0];
    const void*  ei  = d_in[1];
    const float* W1  = (const float*)d_in[2];
    const float* b1  = (const float*)d_in[3];
    const float* W2  = (const float*)d_in[4];
    const float* b2  = (const float*)d_in[5];
    float*       out = (float*)d_out;

    const int N = in_sizes[0] / 128;
    const int E = in_sizes[1] / 2;
    const int nScanBlocks = (N + SCAN_TILE - 1) / SCAN_TILE;

    __half *xw1h, *xw2h;
    float *h, *bf1, *bf2, *dinv;
    cudaGetSymbolAddress((void**)&xw1h, g_xw1h);
    cudaGetSymbolAddress((void**)&h,    g_h);
    cudaGetSymbolAddress((void**)&xw2h, g_xw2h);
    cudaGetSymbolAddress((void**)&bf1,  g_bf1);
    cudaGetSymbolAddress((void**)&bf2,  g_bf2);
    cudaGetSymbolAddress((void**)&dinv, g_dinv);

    // side stream + events: created once on the (uncaptured) correctness call
    static cudaStream_t s2 = nullptr;
    static cudaEvent_t ev1 = nullptr, ev2 = nullptr;
    if (s2 == nullptr) {
        cudaStreamCreateWithFlags(&s2, cudaStreamNonBlocking);
        cudaEventCreateWithFlags(&ev1, cudaEventDisableTiming);
        cudaEventCreateWithFlags(&ev2, cudaEventDisableTiming);
    }

    const int initThreads = (N > BFRAG1 + BFRAG2) ? N : (BFRAG1 + BFRAG2);
    const int eThreads2   = (E + 1) / 2;
    const int gBlocks     = (N + 127) / 128;

    // CSR build prologue (main stream)
    k_init<<<(initThreads + 255) / 256, 256>>>(W1, W2, (const long long*)ei, E, N);
    k_hist<<<(eThreads2 + 255) / 256, 256>>>(ei, E, N);
    k_scan<<<nScanBlocks, 1024>>>(N);

    // fork: gemm1 needs only bfrag + dinv -> run on side stream over scatter
    cudaEventRecord(ev1, 0);
    cudaStreamWaitEvent(s2, ev1, 0);
    k_gemm_tc<128><<<gBlocks, 256, 0, s2>>>(x, bf1, xw1h, dinv, N);
    cudaEventRecord(ev2, s2);

    k_scatter<<<(eThreads2 + 255) / 256, 256>>>(ei, E, N);

    // join, then the dependent tail
    cudaStreamWaitEvent(0, ev2, 0);
    k_agg1<<<(N + 7) / 8, 256>>>(xw1h, b1, h, N, E);
    k_gemm_tc<64><<<gBlocks, 256>>>(h, bf2, xw2h, dinv, N);
    k_agg2<<<(N + 7) / 8, 256>>>(xw2h, b2, out, N, E);
}

// round 15
// speedup vs baseline: 1.1747x; 1.1747x over previous
#include <cuda_runtime.h>
#include <cuda_fp16.h>
#include <math.h>
#include <stdint.h>

// ---------------- problem-size scratch (device globals: allocation-free) ----
#define NMAX 100000
#define EMAX 1600000
#define SCAN_TILE 4096
#define MAX_SCAN_BLOCKS ((NMAX + SCAN_TILE - 1) / SCAN_TILE)
// fp16 B fragment tables: [ksg][nf][lane] x 2 uint32 (b0,b1)
#define BFRAG1H (8 * 16 * 64)
#define BFRAG2H (8 * 8 * 64)

__device__ __half g_xh  [NMAX * 128]; // x in fp16
__device__ __half g_xw1h[NMAX * 128]; // (x @ W1) * dinv[row], fp16
__device__ __half g_hh  [NMAX * 128]; // layer-1 output (post agg+bias+relu), fp16
__device__ __half g_xw2h[NMAX * 64];  // (h @ W2) * dinv[row], fp16
__device__ float  g_dinv[NMAX];       // rsqrt(in_degree + 1)
__device__ int    g_cnt[NMAX];
__device__ int    g_rowptr[NMAX + 1];
__device__ int    g_cursor[NMAX];
__device__ int    g_csr[EMAX];
__device__ int    g_is64;
// packed lookback tile state: bits[63:62] = {0 invalid,1 aggregate,2 inclusive},
// bits[31:0] = value. Single 8-byte word -> flag+value read atomically.
__device__ unsigned long long g_tile[MAX_SCAN_BLOCKS];
__device__ uint32_t g_bfh1[BFRAG1H];  // W1 fp16 mma fragments
__device__ uint32_t g_bfh2[BFRAG2H];  // W2 fp16 mma fragments

// ---------------- mma / async helpers ----------------------------------------
__device__ __forceinline__ uint32_t smem_u32(const void* p) {
    return (uint32_t)__cvta_generic_to_shared(p);
}
__device__ __forceinline__ void ldsm4(uint32_t& r0, uint32_t& r1, uint32_t& r2,
                                      uint32_t& r3, uint32_t a) {
    asm volatile("ldmatrix.sync.aligned.m8n8.x4.shared.b16 {%0,%1,%2,%3}, [%4];"
                 : "=r"(r0), "=r"(r1), "=r"(r2), "=r"(r3) : "r"(a));
}
__device__ __forceinline__ void mma_f16(float c[4], const uint32_t a[4],
                                        uint32_t b0, uint32_t b1) {
    asm volatile("mma.sync.aligned.m16n8k16.row.col.f32.f16.f16.f32 "
                 "{%0,%1,%2,%3}, {%4,%5,%6,%7}, {%8,%9}, {%0,%1,%2,%3};"
                 : "+f"(c[0]), "+f"(c[1]), "+f"(c[2]), "+f"(c[3])
                 : "r"(a[0]), "r"(a[1]), "r"(a[2]), "r"(a[3]), "r"(b0), "r"(b1));
}
__device__ __forceinline__ void cp_async16(uint32_t dst, const void* src, bool pred) {
    int sz = pred ? 16 : 0;
    asm volatile("cp.async.cg.shared.global [%0], [%1], 16, %2;"
                 :: "r"(dst), "l"(src), "r"(sz));
}
__device__ __forceinline__ void cp_commit() {
    asm volatile("cp.async.commit_group;");
}
template <int n>
__device__ __forceinline__ void cp_wait() {
    asm volatile("cp.async.wait_group %0;" :: "n"(n));
}

// ---------------- x -> fp16 conversion (overlappable) ------------------------
__global__ __launch_bounds__(256) void k_cvt(const float* __restrict__ x, int total4) {
    int i = blockIdx.x * blockDim.x + threadIdx.x;
    if (i >= total4) return;
    float4 v = ((const float4*)x)[i];
    uint2 o;
    *(__half2*)&o.x = __floats2half2_rn(v.x, v.y);
    *(__half2*)&o.y = __floats2half2_rn(v.z, v.w);
    ((uint2*)g_xh)[i] = o;
}

// ---------------- fused init: zero cnt + fp16 bfrag + detect + tile reset ----
__global__ void k_init(const float* __restrict__ W1, const float* __restrict__ W2,
                       const long long* __restrict__ ei, int E, int N) {
    int t = blockIdx.x * blockDim.x + threadIdx.x;
    if (t < N) g_cnt[t] = 0;
    if (t < MAX_SCAN_BLOCKS) *((volatile unsigned long long*)&g_tile[t]) = 0ull;
    if (t < BFRAG1H) {
        int j    = t & 1;             // 0 -> b0 (k0-7), 1 -> b1 (k8-15)
        int lane = (t >> 1) & 31;
        int nf   = (t >> 6) & 15;
        int ksg  = t >> 10;           // 0..7
        int k = ksg * 16 + (lane & 3) * 2 + j * 8;
        int n = nf * 8 + (lane >> 2);
        *(__half2*)&g_bfh1[t] = __floats2half2_rn(W1[k * 128 + n], W1[(k + 1) * 128 + n]);
    } else if (t < BFRAG1H + BFRAG2H) {
        int u = t - BFRAG1H;
        int j    = u & 1;
        int lane = (u >> 1) & 31;
        int nf   = (u >> 6) & 7;
        int ksg  = u >> 9;            // 0..7
        int k = ksg * 16 + (lane & 3) * 2 + j * 8;
        int n = nf * 8 + (lane >> 2);
        *(__half2*)&g_bfh2[u] = __floats2half2_rn(W2[k * 64 + n], W2[(k + 1) * 64 + n]);
    }
    if (blockIdx.x == 0 && threadIdx.x < 32) {
        int lane = threadIdx.x;
        int lim = E < 64 ? E : 64;
        bool bad = false;
        for (int j = lane; j < lim; j += 32) {
            long long v = ei[j];
            if (v < 0 || v >= (long long)N) bad = true;
        }
        unsigned m = __ballot_sync(0xffffffffu, bad);
        if (lane == 0) g_is64 = (m == 0) ? 1 : 0;
    }
}

// ---------------- histogram (2 edges/thread, vectorized) ---------------------
__global__ void k_hist(const void* __restrict__ ei, int E, int N) {
    int i = (blockIdx.x * blockDim.x + threadIdx.x) * 2;
    if (i >= E) return;
    int d0, d1 = -1;
    if (g_is64) {
        const long long* p = (const long long*)ei + E;
        if (i + 1 < E) {
            longlong2 v = *(const longlong2*)(p + i);
            d0 = (int)v.x; d1 = (int)v.y;
        } else d0 = (int)p[i];
    } else {
        const int* p = (const int*)ei + E;
        if (i + 1 < E) {
            int2 v = *(const int2*)(p + i);
            d0 = v.x; d1 = v.y;
        } else d0 = p[i];
    }
    if (d0 < 0 || d0 >= N) d0 = 0;
    if (i + 1 < E) {
        if (d1 < 0 || d1 >= N) d1 = 0;
        if (d1 == d0) { atomicAdd(&g_cnt[d0], 2); return; }
        atomicAdd(&g_cnt[d1], 1);
    }
    atomicAdd(&g_cnt[d0], 1);
}

// ---------------- single-pass scan (packed-word decoupled lookback) ----------
__global__ __launch_bounds__(1024) void k_scan(int N) {
    __shared__ int wsum[32];
    __shared__ int s_off;
    const int lane = threadIdx.x & 31;
    const int wid  = threadIdx.x >> 5;
    const int bid  = blockIdx.x;
    const int base = bid * SCAN_TILE + threadIdx.x * 4;

    int v0 = 0, v1 = 0, v2 = 0, v3 = 0;
    if (base + 3 < N) {
        v0 = g_cnt[base]; v1 = g_cnt[base + 1];
        v2 = g_cnt[base + 2]; v3 = g_cnt[base + 3];
    } else {
        if (base     < N) v0 = g_cnt[base];
        if (base + 1 < N) v1 = g_cnt[base + 1];
        if (base + 2 < N) v2 = g_cnt[base + 2];
        if (base + 3 < N) v3 = g_cnt[base + 3];
    }
    int p0 = v0, p1 = p0 + v1, p2 = p1 + v2, p3 = p2 + v3;
    int x = p3;
    #pragma unroll
    for (int o = 1; o < 32; o <<= 1) {
        int y = __shfl_up_sync(0xffffffffu, x, o);
        if (lane >= o) x += y;
    }
    if (lane == 31) wsum[wid] = x;
    __syncthreads();
    if (wid == 0) {
        int w = wsum[lane];
        #pragma unroll
        for (int o = 1; o < 32; o <<= 1) {
            int y = __shfl_up_sync(0xffffffffu, w, o);
            if (lane >= o) w += y;
        }
        wsum[lane] = w;
    }
    __syncthreads();
    int texcl = (x - p3) + (wid ? wsum[wid - 1] : 0);
    int btotal = wsum[31];

    if (threadIdx.x == 0) {
        volatile unsigned long long* tile = (volatile unsigned long long*)g_tile;
        if (bid == 0) {
            tile[0] = (2ull << 62) | (unsigned int)btotal;   // inclusive
            s_off = 0;
        } else {
            tile[bid] = (1ull << 62) | (unsigned int)btotal; // aggregate
            int off = 0;
            for (int p = bid - 1; p >= 0; p--) {
                unsigned long long tv;
                do { tv = tile[p]; } while ((tv >> 62) == 0);
                off += (int)(unsigned int)(tv & 0xffffffffull);
                if ((tv >> 62) == 2) break;
            }
            tile[bid] = (2ull << 62) | (unsigned int)(off + btotal);
            s_off = off;
        }
    }
    __syncthreads();
    int off = s_off;
    if (bid == 0 && threadIdx.x == 0) g_rowptr[0] = 0;
    if (base < N) {
        int incl = off + texcl + p0;
        g_rowptr[base + 1] = incl;
        g_cursor[base]     = incl - v0;
        g_dinv[base]       = rsqrtf((float)(v0 + 1));
    }
    if (base + 1 < N) {
        int incl = off + texcl + p1;
        g_rowptr[base + 2] = incl;
        g_cursor[base + 1] = incl - v1;
        g_dinv[base + 1]   = rsqrtf((float)(v1 + 1));
    }
    if (base + 2 < N) {
        int incl = off + texcl + p2;
        g_rowptr[base + 3] = incl;
        g_cursor[base + 2] = incl - v2;
        g_dinv[base + 2]   = rsqrtf((float)(v2 + 1));
    }
    if (base + 3 < N) {
        int incl = off + texcl + p3;
        g_rowptr[base + 4] = incl;
        g_cursor[base + 3] = incl - v3;
        g_dinv[base + 3]   = rsqrtf((float)(v3 + 1));
    }
}

// ---------------- scatter (2 edges/thread, vectorized reads) -----------------
__global__ void k_scatter(const void* __restrict__ ei, int E, int N) {
    int i = (blockIdx.x * blockDim.x + threadIdx.x) * 2;
    if (i >= E) return;
    int s0, d0, s1 = -1, d1 = -1;
    bool two = (i + 1 < E);
    if (g_is64) {
        const long long* ps = (const long long*)ei;
        const long long* pd = ps + E;
        if (two) {
            longlong2 vs = *(const longlong2*)(ps + i);
            longlong2 vd = *(const longlong2*)(pd + i);
            s0 = (int)vs.x; s1 = (int)vs.y; d0 = (int)vd.x; d1 = (int)vd.y;
        } else { s0 = (int)ps[i]; d0 = (int)pd[i]; }
    } else {
        const int* ps = (const int*)ei;
        const int* pd = ps + E;
        if (two) {
            int2 vs = *(const int2*)(ps + i);
            int2 vd = *(const int2*)(pd + i);
            s0 = vs.x; s1 = vs.y; d0 = vd.x; d1 = vd.y;
        } else { s0 = ps[i]; d0 = pd[i]; }
    }
    if (s0 < 0 || s0 >= N) s0 = 0;
    if (d0 < 0 || d0 >= N) d0 = 0;
    int p0 = atomicAdd(&g_cursor[d0], 1);
    if (p0 >= 0 && p0 < EMAX) g_csr[p0] = s0;
    if (two) {
        if (s1 < 0 || s1 >= N) s1 = 0;
        if (d1 < 0 || d1 >= N) d1 = 0;
        int p1 = atomicAdd(&g_cursor[d1], 1);
        if (p1 >= 0 && p1 < EMAX) g_csr[p1] = s1;
    }
}

// ---------------- fp16 tensor-core GEMM --------------------------------------
// Ch[M,BN] = (A[M,128] @ W) * dinv, fp16 in, fp32 accumulate, fp16 out.
// Full K=128 staged in smem (fp16), 8 x m16n8k16 K-steps.
template <int BN>
__global__ __launch_bounds__(256, 2) void k_gemm_hc(const __half* __restrict__ A,
                                                    const uint32_t* __restrict__ BF,
                                                    __half* __restrict__ C,
                                                    const float* __restrict__ dinv,
                                                    int M) {
    constexpr int NFTOT = BN / 8;
    constexpr int NF    = NFTOT / 2;
    constexpr int LDAH  = 136;        // 128 + 8 pad halves; row stride 272B
    __shared__ __half As[128 * LDAH];

    const int tid  = threadIdx.x;
    const int lane = tid & 31;
    const int wid  = tid >> 5;
    const int wm   = wid & 3;
    const int wn   = wid >> 2;
    const int m0   = blockIdx.x * 128;

    float c[2][NF][4];
    #pragma unroll
    for (int mf = 0; mf < 2; mf++)
        #pragma unroll
        for (int nf = 0; nf < NF; nf++)
            #pragma unroll
            for (int i = 0; i < 4; i++) c[mf][nf][i] = 0.f;

    // stage A: 128 rows x 256B; 16 slots of 16B per row; 8 rows per pass
    {
        const int q  = tid & 15;       // 16B slot
        const int r0 = tid >> 4;       // row 0..15, step 16
        uint32_t sb = smem_u32(As);
        #pragma unroll
        for (int it = 0; it < 8; it++) {
            int r  = r0 + it * 16;
            int gm = m0 + r;
            cp_async16(sb + (r * LDAH + q * 8) * 2,
                       A + (size_t)gm * 128 + q * 8, gm < M);
        }
        cp_commit();
        cp_wait<0>();
        __syncthreads();
    }

    const uint32_t a_base =
        smem_u32(As) + (((wm * 32 + (lane & 15)) * LDAH + (lane >> 4) * 8) << 1);

    #pragma unroll
    for (int ks = 0; ks < 8; ks++) {
        uint32_t a[2][4];
        #pragma unroll
        for (int mf = 0; mf < 2; mf++)
            ldsm4(a[mf][0], a[mf][1], a[mf][2], a[mf][3],
                  a_base + (mf * (16 * LDAH) + ks * 16) * 2);
        #pragma unroll
        for (int nf = 0; nf < NF; nf++) {
            uint2 b = __ldg((const uint2*)BF +
                            (size_t)(ks * NFTOT + wn * NF + nf) * 32 + lane);
            mma_f16(c[0][nf], a[0], b.x, b.y);
            mma_f16(c[1][nf], a[1], b.x, b.y);
        }
    }

    // epilogue: * dinv[row], fp16 store
    #pragma unroll
    for (int mf = 0; mf < 2; mf++) {
        int r0 = m0 + wm * 32 + mf * 16 + (lane >> 2);
        int cb = wn * (BN / 2) + (lane & 3) * 2;
        float d0 = (r0 < M)     ? dinv[r0]     : 0.f;
        float d1 = (r0 + 8 < M) ? dinv[r0 + 8] : 0.f;
        #pragma unroll
        for (int nf = 0; nf < NF; nf++) {
            int n = cb + nf * 8;
            if (r0 < M)
                *(__half2*)(C + (size_t)r0 * BN + n) =
                    __floats2half2_rn(c[mf][nf][0] * d0, c[mf][nf][1] * d0);
            if (r0 + 8 < M)
                *(__half2*)(C + (size_t)(r0 + 8) * BN + n) =
                    __floats2half2_rn(c[mf][nf][2] * d1, c[mf][nf][3] * d1);
        }
    }
}

// ---------------- layer-1 aggregation + bias + ReLU (F=128, fp16 in/out) ----
__global__ __launch_bounds__(256) void k_agg1(const __half* __restrict__ xwh,
                                              const float* __restrict__ bias,
                                              __half* __restrict__ out, int N, int E) {
    int node = blockIdx.x * (blockDim.x >> 5) + (threadIdx.x >> 5);
    if (node >= N) return;
    int lane = threadIdx.x & 31;
    float di = g_dinv[node];

    uint2 u = ((const uint2*)(xwh + (size_t)node * 128))[lane];
    float2 q0 = __half22float2(*(const __half2*)&u.x);
    float2 q1 = __half22float2(*(const __half2*)&u.y);
    float4 acc = make_float4(q0.x, q0.y, q1.x, q1.y);

    int e = g_rowptr[node], end = g_rowptr[node + 1];
    if (e < 0) e = 0;
    if (end > E) end = E;
    for (; e + 1 < end; e += 2) {
        int s0 = g_csr[e], s1 = g_csr[e + 1];
        uint2 a = ((const uint2*)(xwh + (size_t)s0 * 128))[lane];
        uint2 b = ((const uint2*)(xwh + (size_t)s1 * 128))[lane];
        float2 a0 = __half22float2(*(const __half2*)&a.x);
        float2 a1 = __half22float2(*(const __half2*)&a.y);
        float2 b0 = __half22float2(*(const __half2*)&b.x);
        float2 b1 = __half22float2(*(const __half2*)&b.y);
        acc.x += a0.x + b0.x;
        acc.y += a0.y + b0.y;
        acc.z += a1.x + b1.x;
        acc.w += a1.y + b1.y;
    }
    if (e < end) {
        int s = g_csr[e];
        uint2 a = ((const uint2*)(xwh + (size_t)s * 128))[lane];
        float2 a0 = __half22float2(*(const __half2*)&a.x);
        float2 a1 = __half22float2(*(const __half2*)&a.y);
        acc.x += a0.x; acc.y += a0.y; acc.z += a1.x; acc.w += a1.y;
    }
    float4 bb = ((const float4*)bias)[lane];
    float rx = fmaxf(fmaf(acc.x, di, bb.x), 0.f);
    float ry = fmaxf(fmaf(acc.y, di, bb.y), 0.f);
    float rz = fmaxf(fmaf(acc.z, di, bb.z), 0.f);
    float rw = fmaxf(fmaf(acc.w, di, bb.w), 0.f);
    uint2 o;
    *(__half2*)&o.x = __floats2half2_rn(rx, ry);
    *(__half2*)&o.y = __floats2half2_rn(rz, rw);
    ((uint2*)(out + (size_t)node * 128))[lane] = o;
}

// ---------------- layer-2 aggregation + bias + log_softmax (F=64, fp16) -----
__global__ __launch_bounds__(256) void k_agg2(const __half* __restrict__ xwh,
                                              const float* __restrict__ bias,
                                              float* __restrict__ out, int N, int E) {
    int node = blockIdx.x * (blockDim.x >> 5) + (threadIdx.x >> 5);
    if (node >= N) return;
    int lane = threadIdx.x & 31;
    float di = g_dinv[node];

    unsigned u = ((const unsigned*)(xwh + (size_t)node * 64))[lane];
    float2 acc = __half22float2(*(const __half2*)&u);

    int e = g_rowptr[node], end = g_rowptr[node + 1];
    if (e < 0) e = 0;
    if (end > E) end = E;
    for (; e + 1 < end; e += 2) {
        int s0 = g_csr[e], s1 = g_csr[e + 1];
        unsigned a = ((const unsigned*)(xwh + (size_t)s0 * 64))[lane];
        unsigned b = ((const unsigned*)(xwh + (size_t)s1 * 64))[lane];
        float2 av = __half22float2(*(const __half2*)&a);
        float2 bv = __half22float2(*(const __half2*)&b);
        acc.x += av.x + bv.x;
        acc.y += av.y + bv.y;
    }
    if (e < end) {
        int s = g_csr[e];
        unsigned a = ((const unsigned*)(xwh + (size_t)s * 64))[lane];
        float2 av = __half22float2(*(const __half2*)&a);
        acc.x += av.x; acc.y += av.y;
    }
    float2 bb = ((const float2*)bias)[lane];
    float vx = fmaf(acc.x, di, bb.x);
    float vy = fmaf(acc.y, di, bb.y);

    float m = fmaxf(vx, vy);
    #pragma unroll
    for (int o = 16; o; o >>= 1) m = fmaxf(m, __shfl_xor_sync(0xffffffffu, m, o));
    float s = expf(vx - m) + expf(vy - m);
    #pragma unroll
    for (int o = 16; o; o >>= 1) s += __shfl_xor_sync(0xffffffffu, s, o);
    float lse = m + logf(s);
    ((float2*)(out + (size_t)node * 64))[lane] = make_float2(vx - lse, vy - lse);
}

// ---------------- launcher ---------------------------------------------------
extern "C" void kernel_launch(void* const* d_in, const int* in_sizes, int n_in,
                              void* d_out, int out_size) {
    const float* x   = (const float*)d_in[0];
    const void*  ei  = d_in[1];
    const float* W1  = (const float*)d_in[2];
    const float* b1  = (const float*)d_in[3];
    const float* W2  = (const float*)d_in[4];
    const float* b2  = (const float*)d_in[5];
    float*       out = (float*)d_out;

    const int N = in_sizes[0] / 128;
    const int E = in_sizes[1] / 2;
    const int nScanBlocks = (N + SCAN_TILE - 1) / SCAN_TILE;

    __half *xh, *xw1h, *hh, *xw2h;
    float *dinv;
    uint32_t *bfh1, *bfh2;
    cudaGetSymbolAddress((void**)&xh,   g_xh);
    cudaGetSymbolAddress((void**)&xw1h, g_xw1h);
    cudaGetSymbolAddress((void**)&hh,   g_hh);
    cudaGetSymbolAddress((void**)&xw2h, g_xw2h);
    cudaGetSymbolAddress((void**)&dinv, g_dinv);
    cudaGetSymbolAddress((void**)&bfh1, g_bfh1);
    cudaGetSymbolAddress((void**)&bfh2, g_bfh2);

    // side stream + events: created once on the (uncaptured) correctness call
    static cudaStream_t s2 = nullptr;
    static cudaEvent_t ev1 = nullptr, ev2 = nullptr;
    if (s2 == nullptr) {
        cudaStreamCreateWithFlags(&s2, cudaStreamNonBlocking);
        cudaEventCreateWithFlags(&ev1, cudaEventDisableTiming);
        cudaEventCreateWithFlags(&ev2, cudaEventDisableTiming);
    }

    const int initThreads = (N > BFRAG1H + BFRAG2H) ? N : (BFRAG1H + BFRAG2H);
    const int eThreads2   = (E + 1) / 2;
    const int gBlocks     = (N + 127) / 128;
    const int cvt4        = N * 128 / 4;

    // side stream: x -> fp16 (independent; overlaps CSR build)
    k_cvt<<<(cvt4 + 255) / 256, 256, 0, s2>>>(x, cvt4);

    // CSR build prologue (main stream)
    k_init<<<(initThreads + 255) / 256, 256>>>(W1, W2, (const long long*)ei, E, N);
    k_hist<<<(eThreads2 + 255) / 256, 256>>>(ei, E, N);
    k_scan<<<nScanBlocks, 1024>>>(N);

    // fork: gemm1 needs bfrag + dinv + xh -> side stream, overlaps scatter
    cudaEventRecord(ev1, 0);
    cudaStreamWaitEvent(s2, ev1, 0);
    k_gemm_hc<128><<<gBlocks, 256, 0, s2>>>(xh, bfh1, xw1h, dinv, N);
    cudaEventRecord(ev2, s2);

    k_scatter<<<(eThreads2 + 255) / 256, 256>>>(ei, E, N);

    // join, then the dependent tail
    cudaStreamWaitEvent(0, ev2, 0);
    k_agg1<<<(N + 7) / 8, 256>>>(xw1h, b1, hh, N, E);
    k_gemm_hc<64><<<gBlocks, 256>>>(hh, bfh2, xw2h, dinv, N);
    k_agg2<<<(N + 7) / 8, 256>>>(xw2h, b2, out, N, E);
}

// round 16
// speedup vs baseline: 1.2000x; 1.0215x over previous
#include <cuda_runtime.h>
#include <cuda_fp16.h>
#include <math.h>
#include <stdint.h>

// ---------------- problem-size scratch (device globals: allocation-free) ----
#define NMAX 100000
#define EMAX 1600000
#define SCAN_TILE 4096
#define MAX_SCAN_BLOCKS ((NMAX + SCAN_TILE - 1) / SCAN_TILE)   // 25 (<= 32!)
// fp16 B fragment tables: [ksg][nf][lane] x 2 uint32 (b0,b1)
#define BFRAG1H (8 * 16 * 64)
#define BFRAG2H (8 * 8 * 64)

// INVARIANT: g_cnt[] == 0 and g_tile[] == 0 at kernel_launch entry.
// Holds at module load (zero-init) and is restored by k_agg2's epilogue.
__device__ __half g_xh  [NMAX * 128]; // x in fp16
__device__ __half g_xw1h[NMAX * 128]; // (x @ W1) * dinv[row], fp16
__device__ __half g_hh  [NMAX * 128]; // layer-1 output, fp16
__device__ __half g_xw2h[NMAX * 64];  // (h @ W2) * dinv[row], fp16
__device__ float  g_dinv[NMAX];       // rsqrt(in_degree + 1)
__device__ int    g_cnt[NMAX];
__device__ int    g_rowptr[NMAX + 1];
__device__ int    g_cursor[NMAX];
__device__ int    g_csr[EMAX];
// packed lookback tile: bits[63:62] = {0 invalid,1 aggregate,2 inclusive},
// bits[31:0] = value; single 8B word -> flag+value read atomically.
__device__ unsigned long long g_tile[MAX_SCAN_BLOCKS];
__device__ uint32_t g_bfh1[BFRAG1H];  // W1 fp16 mma fragments
__device__ uint32_t g_bfh2[BFRAG2H];  // W2 fp16 mma fragments

// ---------------- helpers -----------------------------------------------------
__device__ __forceinline__ uint32_t smem_u32(const void* p) {
    return (uint32_t)__cvta_generic_to_shared(p);
}
__device__ __forceinline__ void ldsm4(uint32_t& r0, uint32_t& r1, uint32_t& r2,
                                      uint32_t& r3, uint32_t a) {
    asm volatile("ldmatrix.sync.aligned.m8n8.x4.shared.b16 {%0,%1,%2,%3}, [%4];"
                 : "=r"(r0), "=r"(r1), "=r"(r2), "=r"(r3) : "r"(a));
}
__device__ __forceinline__ void mma_f16(float c[4], const uint32_t a[4],
                                        uint32_t b0, uint32_t b1) {
    asm volatile("mma.sync.aligned.m16n8k16.row.col.f32.f16.f16.f32 "
                 "{%0,%1,%2,%3}, {%4,%5,%6,%7}, {%8,%9}, {%0,%1,%2,%3};"
                 : "+f"(c[0]), "+f"(c[1]), "+f"(c[2]), "+f"(c[3])
                 : "r"(a[0]), "r"(a[1]), "r"(a[2]), "r"(a[3]), "r"(b0), "r"(b1));
}
__device__ __forceinline__ void cp_async16(uint32_t dst, const void* src, bool pred) {
    int sz = pred ? 16 : 0;
    asm volatile("cp.async.cg.shared.global [%0], [%1], 16, %2;"
                 :: "r"(dst), "l"(src), "r"(sz));
}
__device__ __forceinline__ void cp_commit() { asm volatile("cp.async.commit_group;"); }
template <int n>
__device__ __forceinline__ void cp_wait() {
    asm volatile("cp.async.wait_group %0;" :: "n"(n));
}
// per-block int64/int32 detection (first 64 entries interpreted as int64)
__device__ __forceinline__ int block_detect64(const void* ei, int E, int N,
                                              int* s_flag) {
    if (threadIdx.x < 32) {
        int lane = threadIdx.x;
        int lim = E < 64 ? E : 64;
        bool bad = false;
        const long long* p = (const long long*)ei;
        for (int j = lane; j < lim; j += 32) {
            long long v = p[j];
            if (v < 0 || v >= (long long)N) bad = true;
        }
        unsigned m = __ballot_sync(0xffffffffu, bad);
        if (lane == 0) *s_flag = (m == 0) ? 1 : 0;
    }
    __syncthreads();
    return *s_flag;
}

// ---------------- side-stream prep -------------------------------------------
__global__ __launch_bounds__(256) void k_cvt(const float* __restrict__ x, int total4) {
    int i = blockIdx.x * blockDim.x + threadIdx.x;
    if (i >= total4) return;
    float4 v = ((const float4*)x)[i];
    uint2 o;
    *(__half2*)&o.x = __floats2half2_rn(v.x, v.y);
    *(__half2*)&o.y = __floats2half2_rn(v.z, v.w);
    ((uint2*)g_xh)[i] = o;
}

__global__ void k_initW(const float* __restrict__ W1, const float* __restrict__ W2) {
    int t = blockIdx.x * blockDim.x + threadIdx.x;
    if (t < BFRAG1H) {
        int j    = t & 1;
        int lane = (t >> 1) & 31;
        int nf   = (t >> 6) & 15;
        int ksg  = t >> 10;
        int k = ksg * 16 + (lane & 3) * 2 + j * 8;
        int n = nf * 8 + (lane >> 2);
        *(__half2*)&g_bfh1[t] = __floats2half2_rn(W1[k * 128 + n], W1[(k + 1) * 128 + n]);
    } else if (t < BFRAG1H + BFRAG2H) {
        int u = t - BFRAG1H;
        int j    = u & 1;
        int lane = (u >> 1) & 31;
        int nf   = (u >> 6) & 7;
        int ksg  = u >> 9;
        int k = ksg * 16 + (lane & 3) * 2 + j * 8;
        int n = nf * 8 + (lane >> 2);
        *(__half2*)&g_bfh2[u] = __floats2half2_rn(W2[k * 64 + n], W2[(k + 1) * 64 + n]);
    }
}

// ---------------- histogram (2 edges/thread, inline detect) ------------------
__global__ void k_hist(const void* __restrict__ ei, int E, int N) {
    __shared__ int s_flag;
    int is64 = block_detect64(ei, E, N, &s_flag);
    int i = (blockIdx.x * blockDim.x + threadIdx.x) * 2;
    if (i >= E) return;
    int d0, d1 = -1;
    if (is64) {
        const long long* p = (const long long*)ei + E;
        if (i + 1 < E) {
            longlong2 v = *(const longlong2*)(p + i);
            d0 = (int)v.x; d1 = (int)v.y;
        } else d0 = (int)p[i];
    } else {
        const int* p = (const int*)ei + E;
        if (i + 1 < E) {
            int2 v = *(const int2*)(p + i);
            d0 = v.x; d1 = v.y;
        } else d0 = p[i];
    }
    if (d0 < 0 || d0 >= N) d0 = 0;
    if (i + 1 < E) {
        if (d1 < 0 || d1 >= N) d1 = 0;
        if (d1 == d0) { atomicAdd(&g_cnt[d0], 2); return; }
        atomicAdd(&g_cnt[d1], 1);
    }
    atomicAdd(&g_cnt[d0], 1);
}

// ---------------- single-pass scan (warp-parallel lookback) ------------------
__global__ __launch_bounds__(1024) void k_scan(int N) {
    __shared__ int wsum[32];
    __shared__ int s_off;
    const int lane = threadIdx.x & 31;
    const int wid  = threadIdx.x >> 5;
    const int bid  = blockIdx.x;
    const int base = bid * SCAN_TILE + threadIdx.x * 4;

    int v0 = 0, v1 = 0, v2 = 0, v3 = 0;
    if (base + 3 < N) {
        v0 = g_cnt[base]; v1 = g_cnt[base + 1];
        v2 = g_cnt[base + 2]; v3 = g_cnt[base + 3];
    } else {
        if (base     < N) v0 = g_cnt[base];
        if (base + 1 < N) v1 = g_cnt[base + 1];
        if (base + 2 < N) v2 = g_cnt[base + 2];
        if (base + 3 < N) v3 = g_cnt[base + 3];
    }
    int p0 = v0, p1 = p0 + v1, p2 = p1 + v2, p3 = p2 + v3;
    int x = p3;
    #pragma unroll
    for (int o = 1; o < 32; o <<= 1) {
        int y = __shfl_up_sync(0xffffffffu, x, o);
        if (lane >= o) x += y;
    }
    if (lane == 31) wsum[wid] = x;
    __syncthreads();
    if (wid == 0) {
        int w = wsum[lane];
        #pragma unroll
        for (int o = 1; o < 32; o <<= 1) {
            int y = __shfl_up_sync(0xffffffffu, w, o);
            if (lane >= o) w += y;
        }
        wsum[lane] = w;
    }
    __syncthreads();
    int texcl = (x - p3) + (wid ? wsum[wid - 1] : 0);
    int btotal = wsum[31];

    // warp-parallel lookback: MAX_SCAN_BLOCKS <= 32 -> one 32-lane window
    if (wid == 0) {
        volatile unsigned long long* tile = (volatile unsigned long long*)g_tile;
        if (bid == 0) {
            if (lane == 0) {
                tile[0] = (2ull << 62) | (unsigned int)btotal;
                s_off = 0;
            }
        } else {
            if (lane == 0) tile[bid] = (1ull << 62) | (unsigned int)btotal;
            __syncwarp();
            int p = bid - 1 - lane;          // lane 0 = nearest predecessor
            bool valid = (p >= 0);
            int st = 0, v = 0;
            if (valid) {
                unsigned long long tv;
                do { tv = tile[p]; } while ((tv >> 62) == 0);
                st = (int)(tv >> 62);
                v  = (int)(unsigned int)(tv & 0xffffffffull);
            }
            unsigned mi = __ballot_sync(0xffffffffu, valid && st == 2);
            int first = __ffs(mi) - 1;       // nearest inclusive (block 0 guarantees mi != 0)
            int contrib = (valid && lane <= first) ? v : 0;
            #pragma unroll
            for (int o = 16; o; o >>= 1)
                contrib += __shfl_xor_sync(0xffffffffu, contrib, o);
            if (lane == 0) {
                tile[bid] = (2ull << 62) | (unsigned int)(contrib + btotal);
                s_off = contrib;
            }
        }
    }
    __syncthreads();
    int off = s_off;
    if (bid == 0 && threadIdx.x == 0) g_rowptr[0] = 0;
    if (base < N) {
        int incl = off + texcl + p0;
        g_rowptr[base + 1] = incl;
        g_cursor[base]     = incl - v0;
        g_dinv[base]       = rsqrtf((float)(v0 + 1));
    }
    if (base + 1 < N) {
        int incl = off + texcl + p1;
        g_rowptr[base + 2] = incl;
        g_cursor[base + 1] = incl - v1;
        g_dinv[base + 1]   = rsqrtf((float)(v1 + 1));
    }
    if (base + 2 < N) {
        int incl = off + texcl + p2;
        g_rowptr[base + 3] = incl;
        g_cursor[base + 2] = incl - v2;
        g_dinv[base + 2]   = rsqrtf((float)(v2 + 1));
    }
    if (base + 3 < N) {
        int incl = off + texcl + p3;
        g_rowptr[base + 4] = incl;
        g_cursor[base + 3] = incl - v3;
        g_dinv[base + 3]   = rsqrtf((float)(v3 + 1));
    }
}

// ---------------- scatter (2 edges/thread, inline detect) --------------------
__global__ void k_scatter(const void* __restrict__ ei, int E, int N) {
    __shared__ int s_flag;
    int is64 = block_detect64(ei, E, N, &s_flag);
    int i = (blockIdx.x * blockDim.x + threadIdx.x) * 2;
    if (i >= E) return;
    int s0, d0, s1 = -1, d1 = -1;
    bool two = (i + 1 < E);
    if (is64) {
        const long long* ps = (const long long*)ei;
        const long long* pd = ps + E;
        if (two) {
            longlong2 vs = *(const longlong2*)(ps + i);
            longlong2 vd = *(const longlong2*)(pd + i);
            s0 = (int)vs.x; s1 = (int)vs.y; d0 = (int)vd.x; d1 = (int)vd.y;
        } else { s0 = (int)ps[i]; d0 = (int)pd[i]; }
    } else {
        const int* ps = (const int*)ei;
        const int* pd = ps + E;
        if (two) {
            int2 vs = *(const int2*)(ps + i);
            int2 vd = *(const int2*)(pd + i);
            s0 = vs.x; s1 = vs.y; d0 = vd.x; d1 = vd.y;
        } else { s0 = ps[i]; d0 = pd[i]; }
    }
    if (s0 < 0 || s0 >= N) s0 = 0;
    if (d0 < 0 || d0 >= N) d0 = 0;
    int p0 = atomicAdd(&g_cursor[d0], 1);
    if (p0 >= 0 && p0 < EMAX) g_csr[p0] = s0;
    if (two) {
        if (s1 < 0 || s1 >= N) s1 = 0;
        if (d1 < 0 || d1 >= N) d1 = 0;
        int p1 = atomicAdd(&g_cursor[d1], 1);
        if (p1 >= 0 && p1 < EMAX) g_csr[p1] = s1;
    }
}

// ---------------- fp16 tensor-core GEMM --------------------------------------
template <int BN>
__global__ __launch_bounds__(256, 2) void k_gemm_hc(const __half* __restrict__ A,
                                                    const uint32_t* __restrict__ BF,
                                                    __half* __restrict__ C,
                                                    const float* __restrict__ dinv,
                                                    int M) {
    constexpr int NFTOT = BN / 8;
    constexpr int NF    = NFTOT / 2;
    constexpr int LDAH  = 136;
    __shared__ __half As[128 * LDAH];

    const int tid  = threadIdx.x;
    const int lane = tid & 31;
    const int wid  = tid >> 5;
    const int wm   = wid & 3;
    const int wn   = wid >> 2;
    const int m0   = blockIdx.x * 128;

    float c[2][NF][4];
    #pragma unroll
    for (int mf = 0; mf < 2; mf++)
        #pragma unroll
        for (int nf = 0; nf < NF; nf++)
            #pragma unroll
            for (int i = 0; i < 4; i++) c[mf][nf][i] = 0.f;

    {
        const int q  = tid & 15;
        const int r0 = tid >> 4;
        uint32_t sb = smem_u32(As);
        #pragma unroll
        for (int it = 0; it < 8; it++) {
            int r  = r0 + it * 16;
            int gm = m0 + r;
            cp_async16(sb + (r * LDAH + q * 8) * 2,
                       A + (size_t)gm * 128 + q * 8, gm < M);
        }
        cp_commit();
        cp_wait<0>();
        __syncthreads();
    }

    const uint32_t a_base =
        smem_u32(As) + (((wm * 32 + (lane & 15)) * LDAH + (lane >> 4) * 8) << 1);

    #pragma unroll
    for (int ks = 0; ks < 8; ks++) {
        uint32_t a[2][4];
        #pragma unroll
        for (int mf = 0; mf < 2; mf++)
            ldsm4(a[mf][0], a[mf][1], a[mf][2], a[mf][3],
                  a_base + (mf * (16 * LDAH) + ks * 16) * 2);
        #pragma unroll
        for (int nf = 0; nf < NF; nf++) {
            uint2 b = __ldg((const uint2*)BF +
                            (size_t)(ks * NFTOT + wn * NF + nf) * 32 + lane);
            mma_f16(c[0][nf], a[0], b.x, b.y);
            mma_f16(c[1][nf], a[1], b.x, b.y);
        }
    }

    #pragma unroll
    for (int mf = 0; mf < 2; mf++) {
        int r0 = m0 + wm * 32 + mf * 16 + (lane >> 2);
        int cb = wn * (BN / 2) + (lane & 3) * 2;
        float d0 = (r0 < M)     ? dinv[r0]     : 0.f;
        float d1 = (r0 + 8 < M) ? dinv[r0 + 8] : 0.f;
        #pragma unroll
        for (int nf = 0; nf < NF; nf++) {
            int n = cb + nf * 8;
            if (r0 < M)
                *(__half2*)(C + (size_t)r0 * BN + n) =
                    __floats2half2_rn(c[mf][nf][0] * d0, c[mf][nf][1] * d0);
            if (r0 + 8 < M)
                *(__half2*)(C + (size_t)(r0 + 8) * BN + n) =
                    __floats2half2_rn(c[mf][nf][2] * d1, c[mf][nf][3] * d1);
        }
    }
}

// ---------------- layer-1 aggregation + bias + ReLU (F=128, 4-edge unroll) --
__global__ __launch_bounds__(256) void k_agg1(const __half* __restrict__ xwh,
                                              const float* __restrict__ bias,
                                              __half* __restrict__ out, int N, int E) {
    int node = blockIdx.x * (blockDim.x >> 5) + (threadIdx.x >> 5);
    if (node >= N) return;
    int lane = threadIdx.x & 31;
    float di = g_dinv[node];

    uint2 u = ((const uint2*)(xwh + (size_t)node * 128))[lane];
    float2 q0 = __half22float2(*(const __half2*)&u.x);
    float2 q1 = __half22float2(*(const __half2*)&u.y);
    float4 acc = make_float4(q0.x, q0.y, q1.x, q1.y);

    int e = g_rowptr[node], end = g_rowptr[node + 1];
    if (e < 0) e = 0;
    if (end > E) end = E;
    for (; e + 3 < end; e += 4) {
        int s0 = g_csr[e], s1 = g_csr[e + 1], s2 = g_csr[e + 2], s3 = g_csr[e + 3];
        uint2 a = ((const uint2*)(xwh + (size_t)s0 * 128))[lane];
        uint2 b = ((const uint2*)(xwh + (size_t)s1 * 128))[lane];
        uint2 cc = ((const uint2*)(xwh + (size_t)s2 * 128))[lane];
        uint2 d = ((const uint2*)(xwh + (size_t)s3 * 128))[lane];
        float2 a0 = __half22float2(*(const __half2*)&a.x);
        float2 a1 = __half22float2(*(const __half2*)&a.y);
        float2 b0 = __half22float2(*(const __half2*)&b.x);
        float2 b1 = __half22float2(*(const __half2*)&b.y);
        float2 c0 = __half22float2(*(const __half2*)&cc.x);
        float2 c1 = __half22float2(*(const __half2*)&cc.y);
        float2 d0 = __half22float2(*(const __half2*)&d.x);
        float2 d1 = __half22float2(*(const __half2*)&d.y);
        acc.x += (a0.x + b0.x) + (c0.x + d0.x);
        acc.y += (a0.y + b0.y) + (c0.y + d0.y);
        acc.z += (a1.x + b1.x) + (c1.x + d1.x);
        acc.w += (a1.y + b1.y) + (c1.y + d1.y);
    }
    for (; e < end; e++) {
        int s = g_csr[e];
        uint2 a = ((const uint2*)(xwh + (size_t)s * 128))[lane];
        float2 a0 = __half22float2(*(const __half2*)&a.x);
        float2 a1 = __half22float2(*(const __half2*)&a.y);
        acc.x += a0.x; acc.y += a0.y; acc.z += a1.x; acc.w += a1.y;
    }
    float4 bb = ((const float4*)bias)[lane];
    float rx = fmaxf(fmaf(acc.x, di, bb.x), 0.f);
    float ry = fmaxf(fmaf(acc.y, di, bb.y), 0.f);
    float rz = fmaxf(fmaf(acc.z, di, bb.z), 0.f);
    float rw = fmaxf(fmaf(acc.w, di, bb.w), 0.f);
    uint2 o;
    *(__half2*)&o.x = __floats2half2_rn(rx, ry);
    *(__half2*)&o.y = __floats2half2_rn(rz, rw);
    ((uint2*)(out + (size_t)node * 128))[lane] = o;
}

// ---------------- layer-2 agg + bias + log_softmax + state reset -------------
__global__ __launch_bounds__(256) void k_agg2(const __half* __restrict__ xwh,
                                              const float* __restrict__ bias,
                                              float* __restrict__ out, int N, int E) {
    // restore the cross-launch invariant for the NEXT replay (cnt/tile zeroed)
    int gtid = blockIdx.x * blockDim.x + threadIdx.x;
    if (gtid < N) g_cnt[gtid] = 0;    // grid has N*32 threads; covers N
    if (gtid < MAX_SCAN_BLOCKS) g_tile[gtid] = 0ull;

    int node = blockIdx.x * (blockDim.x >> 5) + (threadIdx.x >> 5);
    if (node >= N) return;
    int lane = threadIdx.x & 31;
    float di = g_dinv[node];

    unsigned u = ((const unsigned*)(xwh + (size_t)node * 64))[lane];
    float2 acc = __half22float2(*(const __half2*)&u);

    int e = g_rowptr[node], end = g_rowptr[node + 1];
    if (e < 0) e = 0;
    if (end > E) end = E;
    for (; e + 3 < end; e += 4) {
        int s0 = g_csr[e], s1 = g_csr[e + 1], s2 = g_csr[e + 2], s3 = g_csr[e + 3];
        unsigned a = ((const unsigned*)(xwh + (size_t)s0 * 64))[lane];
        unsigned b = ((const unsigned*)(xwh + (size_t)s1 * 64))[lane];
        unsigned c = ((const unsigned*)(xwh + (size_t)s2 * 64))[lane];
        unsigned d = ((const unsigned*)(xwh + (size_t)s3 * 64))[lane];
        float2 av = __half22float2(*(const __half2*)&a);
        float2 bv = __half22float2(*(const __half2*)&b);
        float2 cv = __half22float2(*(const __half2*)&c);
        float2 dv = __half22float2(*(const __half2*)&d);
        acc.x += (av.x + bv.x) + (cv.x + dv.x);
        acc.y += (av.y + bv.y) + (cv.y + dv.y);
    }
    for (; e < end; e++) {
        int s = g_csr[e];
        unsigned a = ((const unsigned*)(xwh + (size_t)s * 64))[lane];
        float2 av = __half22float2(*(const __half2*)&a);
        acc.x += av.x; acc.y += av.y;
    }
    float2 bb = ((const float2*)bias)[lane];
    float vx = fmaf(acc.x, di, bb.x);
    float vy = fmaf(acc.y, di, bb.y);

    float m = fmaxf(vx, vy);
    #pragma unroll
    for (int o = 16; o; o >>= 1) m = fmaxf(m, __shfl_xor_sync(0xffffffffu, m, o));
    float s = expf(vx - m) + expf(vy - m);
    #pragma unroll
    for (int o = 16; o; o >>= 1) s += __shfl_xor_sync(0xffffffffu, s, o);
    float lse = m + logf(s);
    ((float2*)(out + (size_t)node * 64))[lane] = make_float2(vx - lse, vy - lse);
}

// ---------------- launcher ---------------------------------------------------
extern "C" void kernel_launch(void* const* d_in, const int* in_sizes, int n_in,
                              void* d_out, int out_size) {
    const float* x   = (const float*)d_in[0];
    const void*  ei  = d_in[1];
    const float* W1  = (const float*)d_in[2];
    const float* b1  = (const float*)d_in[3];
    const float* W2  = (const float*)d_in[4];
    const float* b2  = (const float*)d_in[5];
    float*       out = (float*)d_out;

    const int N = in_sizes[0] / 128;
    const int E = in_sizes[1] / 2;
    const int nScanBlocks = (N + SCAN_TILE - 1) / SCAN_TILE;

    __half *xh, *xw1h, *hh, *xw2h;
    float *dinv;
    uint32_t *bfh1, *bfh2;
    cudaGetSymbolAddress((void**)&xh,   g_xh);
    cudaGetSymbolAddress((void**)&xw1h, g_xw1h);
    cudaGetSymbolAddress((void**)&hh,   g_hh);
    cudaGetSymbolAddress((void**)&xw2h, g_xw2h);
    cudaGetSymbolAddress((void**)&dinv, g_dinv);
    cudaGetSymbolAddress((void**)&bfh1, g_bfh1);
    cudaGetSymbolAddress((void**)&bfh2, g_bfh2);

    static cudaStream_t s2 = nullptr;
    static cudaEvent_t evScan = nullptr, ev2 = nullptr;
    if (s2 == nullptr) {
        cudaStreamCreateWithFlags(&s2, cudaStreamNonBlocking);
        cudaEventCreateWithFlags(&evScan, cudaEventDisableTiming);
        cudaEventCreateWithFlags(&ev2, cudaEventDisableTiming);
    }

    const int eThreads2 = (E + 1) / 2;
    const int gBlocks   = (N + 127) / 128;
    const int cvt4      = N * 128 / 4;

    // side stream: x->fp16 + W fragment prep (independent of CSR build)
    k_cvt<<<(cvt4 + 255) / 256, 256, 0, s2>>>(x, cvt4);
    k_initW<<<(BFRAG1H + BFRAG2H + 255) / 256, 256, 0, s2>>>(W1, W2);

    // main stream: CSR build (cnt/tile pre-zeroed by previous launch)
    k_hist<<<(eThreads2 + 255) / 256, 256>>>(ei, E, N);
    k_scan<<<nScanBlocks, 1024>>>(N);

    // fork: gemm1 needs xh + bfrag + dinv -> side stream, overlaps scatter
    cudaEventRecord(evScan, 0);
    cudaStreamWaitEvent(s2, evScan, 0);
    k_gemm_hc<128><<<gBlocks, 256, 0, s2>>>(xh, bfh1, xw1h, dinv, N);
    cudaEventRecord(ev2, s2);

    k_scatter<<<(eThreads2 + 255) / 256, 256>>>(ei, E, N);

    // join, then the dependent tail
    cudaStreamWaitEvent(0, ev2, 0);
    k_agg1<<<(N + 7) / 8, 256>>>(xw1h, b1, hh, N, E);
    k_gemm_hc<64><<<gBlocks, 256>>>(hh, bfh2, xw2h, dinv, N);
    k_agg2<<<(N + 7) / 8, 256>>>(xw2h, b2, out, N, E);
}